// round 5
// baseline (speedup 1.0000x reference)
#include <cuda_runtime.h>
#include <cuda_bf16.h>
#include <math.h>

// Problem constants
#define B_ 2
#define T_ 2048
#define E_ 2048
#define H_ 16
#define KVH_ 8
#define D_ 128
#define SCALE_ 0.08838834764831845f   // 1/sqrt(128)

// ---------------- scratch (no allocs allowed) ----------------
__device__ float g_q[(size_t)B_ * T_ * H_ * D_];     // (B,T,H,D)   33.5 MB
__device__ float g_k[(size_t)B_ * T_ * KVH_ * D_];   // (B,T,KVH,D) 16.8 MB
__device__ float g_v[(size_t)B_ * T_ * KVH_ * D_];
__device__ float g_ctx[(size_t)B_ * T_ * H_ * D_];   // attention output

// ---------------- SGEMM: C[M,N] = A[M,K] @ B[K,N], fp32, row-major ----------------
// 128x128 block tile, BK=8, 256 threads, 8x8 per-thread tile.
__global__ __launch_bounds__(256) void sgemm_kernel(
    const float* __restrict__ A, const float* __restrict__ Bm,
    float* __restrict__ C, int M, int N, int K)
{
    __shared__ float As[8][128];
    __shared__ float Bs[8][128];

    const int tid = threadIdx.x;
    const int bx = blockIdx.x;   // N tile
    const int by = blockIdx.y;   // M tile

    const int arow = tid >> 1;          // 0..127
    const int acol = (tid & 1) * 4;     // 0 or 4
    const int brow = tid >> 5;          // 0..7
    const int bcol = (tid & 31) << 2;   // 0..124

    const float* Ag = A + (size_t)(by * 128 + arow) * K + acol;
    const float* Bg = Bm + (size_t)brow * N + bx * 128 + bcol;

    const int tx = tid & 15;
    const int ty = tid >> 4;

    float acc[8][8];
#pragma unroll
    for (int i = 0; i < 8; i++)
#pragma unroll
        for (int j = 0; j < 8; j++) acc[i][j] = 0.0f;

    for (int k0 = 0; k0 < K; k0 += 8) {
        float4 av = *(const float4*)Ag;  Ag += 8;
        float4 bv = *(const float4*)Bg;  Bg += (size_t)8 * N;

        __syncthreads();
        As[acol + 0][arow] = av.x;
        As[acol + 1][arow] = av.y;
        As[acol + 2][arow] = av.z;
        As[acol + 3][arow] = av.w;
        *(float4*)&Bs[brow][bcol] = bv;
        __syncthreads();

#pragma unroll
        for (int kk = 0; kk < 8; kk++) {
            float ar[8], br[8];
            *(float4*)(ar)     = *(float4*)&As[kk][ty * 8];
            *(float4*)(ar + 4) = *(float4*)&As[kk][ty * 8 + 4];
            *(float4*)(br)     = *(float4*)&Bs[kk][tx * 8];
            *(float4*)(br + 4) = *(float4*)&Bs[kk][tx * 8 + 4];
#pragma unroll
            for (int i = 0; i < 8; i++)
#pragma unroll
                for (int j = 0; j < 8; j++)
                    acc[i][j] = fmaf(ar[i], br[j], acc[i][j]);
        }
    }

    float* Cp = C + (size_t)(by * 128 + ty * 8) * N + bx * 128 + tx * 8;
#pragma unroll
    for (int i = 0; i < 8; i++) {
        *(float4*)(Cp + (size_t)i * N)     = make_float4(acc[i][0], acc[i][1], acc[i][2], acc[i][3]);
        *(float4*)(Cp + (size_t)i * N + 4) = make_float4(acc[i][4], acc[i][5], acc[i][6], acc[i][7]);
    }
}

// ---------------- RoPE: x layout (B,T,heads,D), rotate pairs (2i,2i+1) ----------------
__global__ __launch_bounds__(256) void rope_kernel(float* __restrict__ x, int heads, int total_pairs)
{
    int p = blockIdx.x * blockDim.x + threadIdx.x;
    if (p >= total_pairs) return;
    int d2 = p & 63;                       // D/2 = 64
    int t  = (p / (64 * heads)) % T_;

    double inv = pow(10000.0, -(double)(2 * d2) / 128.0);
    double ang = (double)t * inv;
    float c = (float)cos(ang);
    float s = (float)sin(ang);

    float x0 = x[2 * (size_t)p];
    float x1 = x[2 * (size_t)p + 1];
    x[2 * (size_t)p]     = x0 * c - x1 * s;
    x[2 * (size_t)p + 1] = x0 * s + x1 * c;
}

// ---------------- Flash attention (fp32, causal, GQA) ----------------
// grid: (T/64, B*H). block: 256 threads.
// smem: Qs[64][132] Ks[64][132] Vs[64][128] Ps[64][68] + m/l/alpha[64]
#define BR 64
#define BC 64
#define QK_STR 132
#define P_STR  68
#define FLASH_SMEM_FLOATS (64*QK_STR + 64*QK_STR + 64*128 + 64*P_STR + 3*64)

__global__ __launch_bounds__(256) void flash_kernel(
    const float* __restrict__ q, const float* __restrict__ k,
    const float* __restrict__ v, float* __restrict__ ctx)
{
    extern __shared__ float sm[];
    float* Qs  = sm;                        // [64][132]
    float* Ks  = Qs + 64 * QK_STR;          // [64][132]
    float* Vs  = Ks + 64 * QK_STR;          // [64][128]
    float* Ps  = Vs + 64 * 128;             // [64][68]
    float* m_s = Ps + 64 * P_STR;           // [64]
    float* l_s = m_s + 64;                  // [64]
    float* a_s = l_s + 64;                  // [64]

    const int qt = blockIdx.x;
    const int bh = blockIdx.y;
    const int b  = bh / H_;
    const int h  = bh % H_;
    const int g  = h >> 1;                   // kv head (H/KVH = 2)
    const int tid = threadIdx.x;

    // load Q tile (pre-scaled)
    const size_t qbase = (((size_t)b * T_ + (size_t)qt * BR) * H_ + h) * D_;
#pragma unroll
    for (int it = 0; it < 8; ++it) {
        int f  = it * 256 + tid;             // 0..2047
        int r  = f >> 5;
        int d4 = (f & 31) << 2;
        float4 val = *(const float4*)(q + qbase + (size_t)r * (H_ * D_) + d4);
        val.x *= SCALE_; val.y *= SCALE_; val.z *= SCALE_; val.w *= SCALE_;
        *(float4*)&Qs[r * QK_STR + d4] = val;
    }
    if (tid < 64) { m_s[tid] = -1e30f; l_s[tid] = 0.0f; }

    float o[32];
#pragma unroll
    for (int i = 0; i < 32; i++) o[i] = 0.0f;

    const int row = tid >> 2;                // 0..63 (phase B)
    const int dg  = (tid & 3) * 32;          // d offset (phase B)
    const int tx  = tid & 15;                // phase A col group
    const int ty  = tid >> 4;                // phase A row group
    const int r0  = ty * 4;
    const int c0  = tx * 4;

    __syncthreads();

    for (int kt = 0; kt <= qt; ++kt) {
        // ---- load K,V tiles ----
        const size_t kbase = (((size_t)b * T_ + (size_t)kt * BC) * KVH_ + g) * D_;
#pragma unroll
        for (int it = 0; it < 8; ++it) {
            int f  = it * 256 + tid;
            int c  = f >> 5;
            int d4 = (f & 31) << 2;
            size_t off = kbase + (size_t)c * (KVH_ * D_) + d4;
            *(float4*)&Ks[c * QK_STR + d4] = *(const float4*)(k + off);
            *(float4*)&Vs[c * 128    + d4] = *(const float4*)(v + off);
        }
        __syncthreads();

        // ---- phase A: S = Q K^T (4x4 per thread), softmax update ----
        float s[4][4];
#pragma unroll
        for (int i = 0; i < 4; i++)
#pragma unroll
            for (int j = 0; j < 4; j++) s[i][j] = 0.0f;

        for (int k0 = 0; k0 < 128; k0 += 4) {
            float4 qv[4], kv[4];
#pragma unroll
            for (int i = 0; i < 4; i++) qv[i] = *(float4*)&Qs[(r0 + i) * QK_STR + k0];
#pragma unroll
            for (int j = 0; j < 4; j++) kv[j] = *(float4*)&Ks[(c0 + j) * QK_STR + k0];
#pragma unroll
            for (int i = 0; i < 4; i++)
#pragma unroll
                for (int j = 0; j < 4; j++) {
                    s[i][j] = fmaf(qv[i].x, kv[j].x, s[i][j]);
                    s[i][j] = fmaf(qv[i].y, kv[j].y, s[i][j]);
                    s[i][j] = fmaf(qv[i].z, kv[j].z, s[i][j]);
                    s[i][j] = fmaf(qv[i].w, kv[j].w, s[i][j]);
                }
        }

        const bool diag = (kt == qt);
        float mnew[4], rsum[4];
#pragma unroll
        for (int i = 0; i < 4; i++) {
            int qi = qt * BR + r0 + i;
            if (diag) {
#pragma unroll
                for (int j = 0; j < 4; j++)
                    if (kt * BC + c0 + j > qi) s[i][j] = -1e30f;
            }
            float mx = fmaxf(fmaxf(s[i][0], s[i][1]), fmaxf(s[i][2], s[i][3]));
#pragma unroll
            for (int off = 1; off < 16; off <<= 1)
                mx = fmaxf(mx, __shfl_xor_sync(0xffffffffu, mx, off));
            float mo = m_s[r0 + i];
            float mn = fmaxf(mo, mx);
            float sum = 0.0f;
#pragma unroll
            for (int j = 0; j < 4; j++) {
                float p = __expf(s[i][j] - mn);
                s[i][j] = p;
                sum += p;
            }
#pragma unroll
            for (int off = 1; off < 16; off <<= 1)
                sum += __shfl_xor_sync(0xffffffffu, sum, off);
            mnew[i] = mn;
            rsum[i] = sum;
        }
#pragma unroll
        for (int i = 0; i < 4; i++)
            *(float4*)&Ps[(r0 + i) * P_STR + c0] = make_float4(s[i][0], s[i][1], s[i][2], s[i][3]);

        if (tx == 0) {
#pragma unroll
            for (int i = 0; i < 4; i++) {
                float mo = m_s[r0 + i];
                float a  = __expf(mo - mnew[i]);
                a_s[r0 + i] = a;
                l_s[r0 + i] = l_s[r0 + i] * a + rsum[i];
                m_s[r0 + i] = mnew[i];
            }
        }
        __syncthreads();

        // ---- phase B: O = O*alpha + P @ V ----
        float alpha = a_s[row];
#pragma unroll
        for (int i = 0; i < 32; i++) o[i] *= alpha;

#pragma unroll 4
        for (int j = 0; j < BC; j++) {
            float p = Ps[row * P_STR + j];
            const float4* vp = (const float4*)&Vs[j * 128 + dg];
#pragma unroll
            for (int q4 = 0; q4 < 8; q4++) {
                float4 vv = vp[q4];
                o[q4 * 4 + 0] = fmaf(p, vv.x, o[q4 * 4 + 0]);
                o[q4 * 4 + 1] = fmaf(p, vv.y, o[q4 * 4 + 1]);
                o[q4 * 4 + 2] = fmaf(p, vv.z, o[q4 * 4 + 2]);
                o[q4 * 4 + 3] = fmaf(p, vv.w, o[q4 * 4 + 3]);
            }
        }
        __syncthreads();
    }

    // epilogue: normalize and store ctx
    float linv = 1.0f / l_s[row];
    size_t obase = (((size_t)b * T_ + (size_t)qt * BR + row) * H_ + h) * D_ + dg;
#pragma unroll
    for (int q4 = 0; q4 < 8; q4++) {
        float4 val = make_float4(o[q4 * 4 + 0] * linv, o[q4 * 4 + 1] * linv,
                                 o[q4 * 4 + 2] * linv, o[q4 * 4 + 3] * linv);
        *(float4*)(ctx + obase + q4 * 4) = val;
    }
}

// ---------------- launch ----------------
extern "C" void kernel_launch(void* const* d_in, const int* in_sizes, int n_in,
                              void* d_out, int out_size)
{
    const float* x  = (const float*)d_in[0];
    // d_in[1] = mask (int32 causal tril) — implied by flash kernel, unused
    const float* wq = (const float*)d_in[2];
    const float* wk = (const float*)d_in[3];
    const float* wv = (const float*)d_in[4];
    const float* wo = (const float*)d_in[5];
    float* out = (float*)d_out;

    float *gq, *gk, *gv, *gctx;
    cudaGetSymbolAddress((void**)&gq,   g_q);
    cudaGetSymbolAddress((void**)&gk,   g_k);
    cudaGetSymbolAddress((void**)&gv,   g_v);
    cudaGetSymbolAddress((void**)&gctx, g_ctx);

    const int M = B_ * T_;  // 4096

    // projections
    sgemm_kernel<<<dim3((H_ * D_) / 128, M / 128), 256>>>(x, wq, gq, M, H_ * D_, E_);
    sgemm_kernel<<<dim3((KVH_ * D_) / 128, M / 128), 256>>>(x, wk, gk, M, KVH_ * D_, E_);
    sgemm_kernel<<<dim3((KVH_ * D_) / 128, M / 128), 256>>>(x, wv, gv, M, KVH_ * D_, E_);

    // rope
    int npq = B_ * T_ * H_ * (D_ / 2);    // 4,194,304
    int npk = B_ * T_ * KVH_ * (D_ / 2);  // 2,097,152
    rope_kernel<<<npq / 256, 256>>>(gq, H_, npq);
    rope_kernel<<<npk / 256, 256>>>(gk, KVH_, npk);

    // attention
    const int flash_smem = FLASH_SMEM_FLOATS * sizeof(float);
    cudaFuncSetAttribute(flash_kernel, cudaFuncAttributeMaxDynamicSharedMemorySize, flash_smem);
    flash_kernel<<<dim3(T_ / BR, B_ * H_), 256, flash_smem>>>(gq, gk, gv, gctx);

    // output projection
    sgemm_kernel<<<dim3(E_ / 128, M / 128), 256>>>(gctx, wo, out, M, E_, H_ * D_);
}

// round 6
// speedup vs baseline: 2.6747x; 2.6747x over previous
#include <cuda_runtime.h>
#include <cuda_bf16.h>
#include <math.h>

// Problem constants
#define B_ 2
#define T_ 2048
#define E_ 2048
#define H_ 16
#define KVH_ 8
#define D_ 128
#define SCALE_ 0.08838834764831845f   // 1/sqrt(128)

typedef unsigned long long ull;

// ---------------- packed f32x2 helpers (Blackwell FFMA2 pipe) ----------------
__device__ __forceinline__ ull pk2(float lo, float hi) {
    ull r; asm("mov.b64 %0, {%1, %2};" : "=l"(r) : "f"(lo), "f"(hi)); return r;
}
__device__ __forceinline__ void upk2(ull v, float& lo, float& hi) {
    asm("mov.b64 {%0, %1}, %2;" : "=f"(lo), "=f"(hi) : "l"(v));
}
__device__ __forceinline__ void fma2(ull& d, ull a, ull b) {
    asm("fma.rn.f32x2 %0, %1, %2, %0;" : "+l"(d) : "l"(a), "l"(b));
}
__device__ __forceinline__ void mul2(ull& d, ull a) {
    asm("mul.rn.f32x2 %0, %0, %1;" : "+l"(d) : "l"(a));
}

// ---------------- scratch (no allocs allowed) ----------------
__device__ float g_q[(size_t)B_ * T_ * H_ * D_];     // (B,T,H,D)
__device__ float g_k[(size_t)B_ * T_ * KVH_ * D_];   // (B,T,KVH,D)
__device__ float g_v[(size_t)B_ * T_ * KVH_ * D_];
__device__ float g_ctx[(size_t)B_ * T_ * H_ * D_];   // attention output
__device__ float2 g_rope[T_ * 64];                   // (cos,sin) per (t,d2)

// ---------------- RoPE table (one-time-per-launch, double precision) ----------------
__global__ __launch_bounds__(256) void rope_table_kernel() {
    int idx = blockIdx.x * 256 + threadIdx.x;  // 131072 total
    int t = idx >> 6, d2 = idx & 63;
    double inv = pow(10000.0, -(double)(2 * d2) / 128.0);
    double ang = (double)t * inv;
    g_rope[idx] = make_float2((float)cos(ang), (float)sin(ang));
}

// ---------------- RoPE apply: x (B,T,heads,D), float4 = 2 rotation pairs ----------------
__global__ __launch_bounds__(256) void rope_apply_kernel(float* __restrict__ x, int heads, int total4) {
    int p = blockIdx.x * 256 + threadIdx.x;
    if (p >= total4) return;
    int cd = p & 31;                       // float4 chunk within D (0..31)
    int t = (p / (32 * heads)) % T_;
    float4 v = ((const float4*)x)[p];
    float2 r0 = g_rope[t * 64 + cd * 2];
    float2 r1 = g_rope[t * 64 + cd * 2 + 1];
    float a = v.x * r0.x - v.y * r0.y;
    float b = v.x * r0.y + v.y * r0.x;
    float c = v.z * r1.x - v.w * r1.y;
    float d = v.z * r1.y + v.w * r1.x;
    ((float4*)x)[p] = make_float4(a, b, c, d);
}

// ---------------- SGEMM: C[M,N] = A[M,K] @ B[K,N], fp32 via FFMA2 ----------------
// 128x128 tile, BK=8, 256 threads, 8x8 per thread (packed 8x4 u64), double-buffered.
__device__ __forceinline__ void sgemm_compute(
    const float As[8][128], const float Bs[8][128],
    int ty, int tx, ull acc[8][4])
{
#pragma unroll
    for (int kk = 0; kk < 8; kk++) {
        float ar[8];
        *(float4*)(ar)     = *(const float4*)&As[kk][ty * 8];
        *(float4*)(ar + 4) = *(const float4*)&As[kk][ty * 8 + 4];
        ulonglong2 b0 = *(const ulonglong2*)&Bs[kk][tx * 8];
        ulonglong2 b1 = *(const ulonglong2*)&Bs[kk][tx * 8 + 4];
        ull br0 = b0.x, br1 = b0.y, br2 = b1.x, br3 = b1.y;
#pragma unroll
        for (int i = 0; i < 8; i++) {
            ull a2 = pk2(ar[i], ar[i]);
            fma2(acc[i][0], a2, br0);
            fma2(acc[i][1], a2, br1);
            fma2(acc[i][2], a2, br2);
            fma2(acc[i][3], a2, br3);
        }
    }
}

__global__ __launch_bounds__(256) void sgemm_kernel(
    const float* __restrict__ A, const float* __restrict__ Bm,
    float* __restrict__ C, int M, int N, int K)
{
    __shared__ float As[2][8][128];
    __shared__ float Bs[2][8][128];

    const int tid = threadIdx.x;
    const int bx = blockIdx.x, by = blockIdx.y;
    const int arow = tid >> 1;
    const int acol = (tid & 1) * 4;
    const int brow = tid >> 5;
    const int bcol = (tid & 31) << 2;
    const int tx = tid & 15, ty = tid >> 4;

    const float* Ag = A + (size_t)(by * 128 + arow) * K + acol;
    const float* Bg = Bm + (size_t)brow * N + bx * 128 + bcol;

    ull acc[8][4];
#pragma unroll
    for (int i = 0; i < 8; i++)
#pragma unroll
        for (int j = 0; j < 4; j++) acc[i][j] = 0ull;

    // preload chunk 0
    float4 av = *(const float4*)Ag;  Ag += 8;
    float4 bv = *(const float4*)Bg;  Bg += (size_t)8 * N;
    As[0][acol + 0][arow] = av.x;
    As[0][acol + 1][arow] = av.y;
    As[0][acol + 2][arow] = av.z;
    As[0][acol + 3][arow] = av.w;
    *(float4*)&Bs[0][brow][bcol] = bv;
    __syncthreads();

    const int nch = K >> 3;
    for (int c = 1; c < nch; ++c) {
        av = *(const float4*)Ag;  Ag += 8;
        bv = *(const float4*)Bg;  Bg += (size_t)8 * N;
        const int cur = (c - 1) & 1;
        sgemm_compute(As[cur], Bs[cur], ty, tx, acc);
        const int nxt = c & 1;
        As[nxt][acol + 0][arow] = av.x;
        As[nxt][acol + 1][arow] = av.y;
        As[nxt][acol + 2][arow] = av.z;
        As[nxt][acol + 3][arow] = av.w;
        *(float4*)&Bs[nxt][brow][bcol] = bv;
        __syncthreads();
    }
    sgemm_compute(As[(nch - 1) & 1], Bs[(nch - 1) & 1], ty, tx, acc);

    float* Cp = C + (size_t)(by * 128 + ty * 8) * N + bx * 128 + tx * 8;
#pragma unroll
    for (int i = 0; i < 8; i++) {
        float cf[8];
#pragma unroll
        for (int j = 0; j < 4; j++) upk2(acc[i][j], cf[2 * j], cf[2 * j + 1]);
        *(float4*)(Cp + (size_t)i * N)     = make_float4(cf[0], cf[1], cf[2], cf[3]);
        *(float4*)(Cp + (size_t)i * N + 4) = make_float4(cf[4], cf[5], cf[6], cf[7]);
    }
}

// ---------------- Flash attention: 128x128 tiles, FFMA2, swizzled smem ----------------
// grid (T/128, B*H), 256 threads (16x16), 8x8 per thread in both phases.
// smem: Qt[128][128] (TRANSPOSED: [k][r]), KP[128][128] (K tile, reused as P), Vs[128][128],
// all XOR-swizzled at float4 granularity: phys_chunk = chunk ^ ((row>>3)&7).
#define FT 128
#define FLASH_SMEM_FLOATS (3 * 128 * 128 + 3 * 128)

__global__ __launch_bounds__(256) void flash_kernel(
    const float* __restrict__ q, const float* __restrict__ k,
    const float* __restrict__ v, float* __restrict__ ctx)
{
    extern __shared__ float sm[];
    float* Qt  = sm;                 // [128][128] transposed [d][r], swizzled
    float* KP  = sm + 16384;         // [128][128] K rows then P rows, swizzled
    float* Vs  = sm + 32768;         // [128][128] V rows, swizzled
    float* m_s = sm + 49152;
    float* l_s = m_s + 128;
    float* a_s = l_s + 128;

    const int qt_ = (int)gridDim.x - 1 - (int)blockIdx.x;  // heavy blocks first
    const int bh = blockIdx.y;
    const int b = bh >> 4;
    const int h = bh & 15;
    const int g = h >> 1;                    // kv head (H/KVH = 2)
    const int tid = threadIdx.x;
    const int tx = tid & 15, ty = tid >> 4;
    const int r0 = ty * 8, c0 = tx * 8;

    // ---- load Q tile, pre-scale, store TRANSPOSED ([d][r]) with swizzle ----
    const size_t qbase = (((size_t)b * T_ + (size_t)qt_ * FT) * H_ + h) * D_;
#pragma unroll
    for (int it = 0; it < 16; ++it) {
        int f = it * 256 + tid;
        int r = f >> 5, cd = f & 31;
        float4 val = *(const float4*)(q + qbase + (size_t)r * (H_ * D_) + cd * 4);
        val.x *= SCALE_; val.y *= SCALE_; val.z *= SCALE_; val.w *= SCALE_;
        int d0 = cd * 4;
        int rlow = r & 3, rch = r >> 2;
        Qt[(d0 + 0) * 128 + (((rch ^ (((d0 + 0) >> 3) & 7)) << 2) | rlow)] = val.x;
        Qt[(d0 + 1) * 128 + (((rch ^ (((d0 + 1) >> 3) & 7)) << 2) | rlow)] = val.y;
        Qt[(d0 + 2) * 128 + (((rch ^ (((d0 + 2) >> 3) & 7)) << 2) | rlow)] = val.z;
        Qt[(d0 + 3) * 128 + (((rch ^ (((d0 + 3) >> 3) & 7)) << 2) | rlow)] = val.w;
    }
    if (tid < 128) { m_s[tid] = -1e30f; l_s[tid] = 0.0f; }

    ull o2[8][4];
#pragma unroll
    for (int i = 0; i < 8; i++)
#pragma unroll
        for (int j = 0; j < 4; j++) o2[i][j] = 0ull;

    __syncthreads();

    for (int kt = 0; kt <= qt_; ++kt) {
        // ---- load K,V tiles (row-major, swizzled) ----
        const size_t kvbase = (((size_t)b * T_ + (size_t)kt * FT) * KVH_ + g) * D_;
#pragma unroll
        for (int it = 0; it < 16; ++it) {
            int f = it * 256 + tid;
            int r = f >> 5, cd = f & 31;
            size_t off = kvbase + (size_t)r * (KVH_ * D_) + cd * 4;
            int sidx = r * 32 + (cd ^ ((r >> 3) & 7));
            ((float4*)KP)[sidx] = *(const float4*)(k + off);
            ((float4*)Vs)[sidx] = *(const float4*)(v + off);
        }
        __syncthreads();

        // ---- phase A: S = Q K^T, packed along query rows ----
        ull s2[4][8];
#pragma unroll
        for (int i = 0; i < 4; i++)
#pragma unroll
            for (int j = 0; j < 8; j++) s2[i][j] = 0ull;

#pragma unroll 2
        for (int kc = 0; kc < 32; ++kc) {
            float kf[8][4];
#pragma unroll
            for (int j = 0; j < 8; ++j) {
                int c = c0 + j;
                *(float4*)kf[j] = ((const float4*)KP)[c * 32 + (kc ^ ((c >> 3) & 7))];
            }
#pragma unroll
            for (int kk = 0; kk < 4; ++kk) {
                int kd = kc * 4 + kk;
                int s_ = (kd >> 3) & 7;
                ulonglong2 qa = ((const ulonglong2*)Qt)[kd * 32 + ((ty * 2) ^ s_)];
                ulonglong2 qb = ((const ulonglong2*)Qt)[kd * 32 + ((ty * 2 + 1) ^ s_)];
#pragma unroll
                for (int j = 0; j < 8; ++j) {
                    ull kdp = pk2(kf[j][kk], kf[j][kk]);
                    fma2(s2[0][j], qa.x, kdp);
                    fma2(s2[1][j], qa.y, kdp);
                    fma2(s2[2][j], qb.x, kdp);
                    fma2(s2[3][j], qb.y, kdp);
                }
            }
        }

        // ---- unpack, mask, online softmax ----
        float sf[8][8];
#pragma unroll
        for (int i2 = 0; i2 < 4; i2++)
#pragma unroll
            for (int j = 0; j < 8; j++)
                upk2(s2[i2][j], sf[2 * i2][j], sf[2 * i2 + 1][j]);

        const bool diag = (kt == qt_);
#pragma unroll
        for (int i = 0; i < 8; ++i) {
            if (diag) {
                int qi = qt_ * FT + r0 + i;
#pragma unroll
                for (int j = 0; j < 8; ++j)
                    if (kt * FT + c0 + j > qi) sf[i][j] = -1e30f;
            }
            float mx = sf[i][0];
#pragma unroll
            for (int j = 1; j < 8; ++j) mx = fmaxf(mx, sf[i][j]);
#pragma unroll
            for (int off = 1; off < 16; off <<= 1)
                mx = fmaxf(mx, __shfl_xor_sync(0xffffffffu, mx, off));
            float mo = m_s[r0 + i];
            float mn = fmaxf(mo, mx);
            float sum = 0.0f;
#pragma unroll
            for (int j = 0; j < 8; ++j) {
                float p = __expf(sf[i][j] - mn);
                sf[i][j] = p;
                sum += p;
            }
#pragma unroll
            for (int off = 1; off < 16; off <<= 1)
                sum += __shfl_xor_sync(0xffffffffu, sum, off);
            if (tx == 0) {
                float al = __expf(mo - mn);
                a_s[r0 + i] = al;
                l_s[r0 + i] = l_s[r0 + i] * al + sum;
                m_s[r0 + i] = mn;
            }
        }
        __syncthreads();   // all warps done reading KP as K

        // ---- store P into KP buffer (own-warp rows) ----
#pragma unroll
        for (int i = 0; i < 8; ++i) {
            int r = r0 + i, s_ = (r >> 3) & 7;
            ((float4*)KP)[r * 32 + ((tx * 2) ^ s_)]     = make_float4(sf[i][0], sf[i][1], sf[i][2], sf[i][3]);
            ((float4*)KP)[r * 32 + ((tx * 2 + 1) ^ s_)] = make_float4(sf[i][4], sf[i][5], sf[i][6], sf[i][7]);
        }
        __syncwarp();      // P rows are written/read within the same warp only

        // ---- phase B: O = O*alpha + P @ V, packed along d ----
#pragma unroll
        for (int i = 0; i < 8; ++i) {
            float al = a_s[r0 + i];
            ull ap = pk2(al, al);
#pragma unroll
            for (int d2 = 0; d2 < 4; ++d2) mul2(o2[i][d2], ap);
        }

#pragma unroll 2
        for (int jc = 0; jc < 32; ++jc) {
            float pv[8][4];
#pragma unroll
            for (int i = 0; i < 8; ++i) {
                int r = r0 + i;
                *(float4*)pv[i] = ((const float4*)KP)[r * 32 + (jc ^ ((r >> 3) & 7))];
            }
            ull vv[4][4];
#pragma unroll
            for (int jj = 0; jj < 4; ++jj) {
                int r = jc * 4 + jj, s_ = (r >> 3) & 7;
                ulonglong2 va = ((const ulonglong2*)Vs)[r * 32 + ((tx * 2) ^ s_)];
                ulonglong2 vb = ((const ulonglong2*)Vs)[r * 32 + ((tx * 2 + 1) ^ s_)];
                vv[jj][0] = va.x; vv[jj][1] = va.y; vv[jj][2] = vb.x; vv[jj][3] = vb.y;
            }
#pragma unroll
            for (int jj = 0; jj < 4; ++jj)
#pragma unroll
                for (int i = 0; i < 8; ++i) {
                    ull pa = pk2(pv[i][jj], pv[i][jj]);
                    fma2(o2[i][0], pa, vv[jj][0]);
                    fma2(o2[i][1], pa, vv[jj][1]);
                    fma2(o2[i][2], pa, vv[jj][2]);
                    fma2(o2[i][3], pa, vv[jj][3]);
                }
        }
        __syncthreads();   // before next tile overwrites KP/Vs
    }

    // ---- epilogue: normalize + store ctx (B,T,H*D) ----
    const size_t obase = (((size_t)b * T_ + (size_t)qt_ * FT + r0) * H_ + h) * D_ + c0;
#pragma unroll
    for (int i = 0; i < 8; ++i) {
        float linv = 1.0f / l_s[r0 + i];
        float of[8];
#pragma unroll
        for (int d2 = 0; d2 < 4; ++d2) upk2(o2[i][d2], of[2 * d2], of[2 * d2 + 1]);
#pragma unroll
        for (int e = 0; e < 8; ++e) of[e] *= linv;
        *(float4*)(ctx + obase + (size_t)i * (H_ * D_))     = make_float4(of[0], of[1], of[2], of[3]);
        *(float4*)(ctx + obase + (size_t)i * (H_ * D_) + 4) = make_float4(of[4], of[5], of[6], of[7]);
    }
}

// ---------------- launch ----------------
extern "C" void kernel_launch(void* const* d_in, const int* in_sizes, int n_in,
                              void* d_out, int out_size)
{
    const float* x  = (const float*)d_in[0];
    // d_in[1] = mask (int32 causal tril) — implied by flash kernel, unused
    const float* wq = (const float*)d_in[2];
    const float* wk = (const float*)d_in[3];
    const float* wv = (const float*)d_in[4];
    const float* wo = (const float*)d_in[5];
    float* out = (float*)d_out;

    float *gq, *gk, *gv, *gctx;
    cudaGetSymbolAddress((void**)&gq,   g_q);
    cudaGetSymbolAddress((void**)&gk,   g_k);
    cudaGetSymbolAddress((void**)&gv,   g_v);
    cudaGetSymbolAddress((void**)&gctx, g_ctx);

    const int M = B_ * T_;  // 4096

    // rope table (independent of GEMMs)
    rope_table_kernel<<<(T_ * 64) / 256, 256>>>();

    // projections
    sgemm_kernel<<<dim3((H_ * D_) / 128, M / 128), 256>>>(x, wq, gq, M, H_ * D_, E_);
    sgemm_kernel<<<dim3((KVH_ * D_) / 128, M / 128), 256>>>(x, wk, gk, M, KVH_ * D_, E_);
    sgemm_kernel<<<dim3((KVH_ * D_) / 128, M / 128), 256>>>(x, wv, gv, M, KVH_ * D_, E_);

    // rope apply
    int nq4 = B_ * T_ * H_ * (D_ / 4);    // 2,097,152
    int nk4 = B_ * T_ * KVH_ * (D_ / 4);  // 1,048,576
    rope_apply_kernel<<<nq4 / 256, 256>>>(gq, H_, nq4);
    rope_apply_kernel<<<nk4 / 256, 256>>>(gk, KVH_, nk4);

    // attention
    const int flash_smem = FLASH_SMEM_FLOATS * sizeof(float);
    cudaFuncSetAttribute(flash_kernel, cudaFuncAttributeMaxDynamicSharedMemorySize, flash_smem);
    flash_kernel<<<dim3(T_ / FT, B_ * H_), 256, flash_smem>>>(gq, gk, gv, gctx);

    // output projection
    sgemm_kernel<<<dim3(E_ / 128, M / 128), 256>>>(gctx, wo, out, M, E_, H_ * D_);
}

// round 7
// speedup vs baseline: 2.7290x; 1.0203x over previous
#include <cuda_runtime.h>
#include <cuda_bf16.h>
#include <math.h>

// Problem constants
#define B_ 2
#define T_ 2048
#define E_ 2048
#define H_ 16
#define KVH_ 8
#define D_ 128
#define SCALE_ 0.08838834764831845f   // 1/sqrt(128)

typedef unsigned long long ull;

// ---------------- packed f32x2 helpers (Blackwell FFMA2 pipe, rt_SMSP=1) ----------------
__device__ __forceinline__ ull pk2(float lo, float hi) {
    ull r; asm("mov.b64 %0, {%1, %2};" : "=l"(r) : "f"(lo), "f"(hi)); return r;
}
__device__ __forceinline__ void upk2(ull v, float& lo, float& hi) {
    asm("mov.b64 {%0, %1}, %2;" : "=f"(lo), "=f"(hi) : "l"(v));
}
__device__ __forceinline__ void fma2(ull& d, ull a, ull b) {
    asm("fma.rn.f32x2 %0, %1, %2, %0;" : "+l"(d) : "l"(a), "l"(b));
}
__device__ __forceinline__ void mul2(ull& d, ull a) {
    asm("mul.rn.f32x2 %0, %0, %1;" : "+l"(d) : "l"(a));
}

// ---------------- scratch (no allocs allowed) ----------------
__device__ float g_q[(size_t)B_ * T_ * H_ * D_];     // (B,T,H,D)
__device__ float g_k[(size_t)B_ * T_ * KVH_ * D_];   // (B,T,KVH,D)
__device__ float g_v[(size_t)B_ * T_ * KVH_ * D_];
__device__ float g_ctx[(size_t)B_ * T_ * H_ * D_];   // attention output
__device__ float2 g_rope[T_ * 64];                   // (cos,sin) per (t,d2)

// ---------------- RoPE table ----------------
__global__ __launch_bounds__(256) void rope_table_kernel() {
    int idx = blockIdx.x * 256 + threadIdx.x;  // 131072 total
    int t = idx >> 6, d2 = idx & 63;
    double inv = pow(10000.0, -(double)(2 * d2) / 128.0);
    double ang = (double)t * inv;
    g_rope[idx] = make_float2((float)cos(ang), (float)sin(ang));
}

// ---------------- RoPE apply: x (B,T,heads,D), float4 = 2 rotation pairs ----------------
__global__ __launch_bounds__(256) void rope_apply_kernel(float* __restrict__ x, int heads, int total4) {
    int p = blockIdx.x * 256 + threadIdx.x;
    if (p >= total4) return;
    int cd = p & 31;
    int t = (p / (32 * heads)) % T_;
    float4 v = ((const float4*)x)[p];
    float2 r0 = g_rope[t * 64 + cd * 2];
    float2 r1 = g_rope[t * 64 + cd * 2 + 1];
    float a = v.x * r0.x - v.y * r0.y;
    float b = v.x * r0.y + v.y * r0.x;
    float c = v.z * r1.x - v.w * r1.y;
    float d = v.z * r1.y + v.w * r1.x;
    ((float4*)x)[p] = make_float4(a, b, c, d);
}

// ---------------- SGEMM: C[M,N] = A[M,K] @ B[K,N], fp32 via FFMA2 ----------------
// 128x128 tile, BK=16, 256 threads, 8x8 per thread, double-buffered, As padded.
__device__ __forceinline__ void sgemm_compute(
    const float As[16][132], const float Bs[16][128],
    int ty, int tx, ull acc[8][4])
{
#pragma unroll
    for (int kk = 0; kk < 16; kk++) {
        float ar[8];
        *(float4*)(ar)     = *(const float4*)&As[kk][ty * 8];
        *(float4*)(ar + 4) = *(const float4*)&As[kk][ty * 8 + 4];
        ulonglong2 b0 = *(const ulonglong2*)&Bs[kk][tx * 8];
        ulonglong2 b1 = *(const ulonglong2*)&Bs[kk][tx * 8 + 4];
        ull br0 = b0.x, br1 = b0.y, br2 = b1.x, br3 = b1.y;
#pragma unroll
        for (int i = 0; i < 8; i++) {
            ull a2 = pk2(ar[i], ar[i]);
            fma2(acc[i][0], a2, br0);
            fma2(acc[i][1], a2, br1);
            fma2(acc[i][2], a2, br2);
            fma2(acc[i][3], a2, br3);
        }
    }
}

__global__ __launch_bounds__(256, 2) void sgemm_kernel(
    const float* __restrict__ A, const float* __restrict__ Bm,
    float* __restrict__ C, int M, int N, int K)
{
    __shared__ float As[2][16][132];
    __shared__ float Bs[2][16][128];

    const int tid = threadIdx.x;
    const int bx = blockIdx.x, by = blockIdx.y;
    const int arow = tid >> 2;          // 0..63  (second half: +64)
    const int acol = (tid & 3) * 4;     // k-offset within chunk
    const int brow = tid >> 5;          // 0..7   (second half: +8)
    const int bcol = (tid & 31) << 2;
    const int tx = tid & 15, ty = tid >> 4;

    const float* Ag = A + (size_t)(by * 128 + arow) * K + acol;
    const float* Bg = Bm + (size_t)brow * N + bx * 128 + bcol;

    ull acc[8][4];
#pragma unroll
    for (int i = 0; i < 8; i++)
#pragma unroll
        for (int j = 0; j < 4; j++) acc[i][j] = 0ull;

    // preload chunk 0
    float4 av0 = *(const float4*)Ag;
    float4 av1 = *(const float4*)(Ag + (size_t)64 * K);
    Ag += 16;
    float4 bv0 = *(const float4*)Bg;
    float4 bv1 = *(const float4*)(Bg + (size_t)8 * N);
    Bg += (size_t)16 * N;
    As[0][acol + 0][arow] = av0.x;  As[0][acol + 1][arow] = av0.y;
    As[0][acol + 2][arow] = av0.z;  As[0][acol + 3][arow] = av0.w;
    As[0][acol + 0][arow + 64] = av1.x;  As[0][acol + 1][arow + 64] = av1.y;
    As[0][acol + 2][arow + 64] = av1.z;  As[0][acol + 3][arow + 64] = av1.w;
    *(float4*)&Bs[0][brow][bcol] = bv0;
    *(float4*)&Bs[0][brow + 8][bcol] = bv1;
    __syncthreads();

    const int nch = K >> 4;
    for (int c = 1; c < nch; ++c) {
        av0 = *(const float4*)Ag;
        av1 = *(const float4*)(Ag + (size_t)64 * K);
        Ag += 16;
        bv0 = *(const float4*)Bg;
        bv1 = *(const float4*)(Bg + (size_t)8 * N);
        Bg += (size_t)16 * N;
        const int cur = (c - 1) & 1;
        sgemm_compute(As[cur], Bs[cur], ty, tx, acc);
        const int nxt = c & 1;
        As[nxt][acol + 0][arow] = av0.x;  As[nxt][acol + 1][arow] = av0.y;
        As[nxt][acol + 2][arow] = av0.z;  As[nxt][acol + 3][arow] = av0.w;
        As[nxt][acol + 0][arow + 64] = av1.x;  As[nxt][acol + 1][arow + 64] = av1.y;
        As[nxt][acol + 2][arow + 64] = av1.z;  As[nxt][acol + 3][arow + 64] = av1.w;
        *(float4*)&Bs[nxt][brow][bcol] = bv0;
        *(float4*)&Bs[nxt][brow + 8][bcol] = bv1;
        __syncthreads();
    }
    sgemm_compute(As[(nch - 1) & 1], Bs[(nch - 1) & 1], ty, tx, acc);

    float* Cp = C + (size_t)(by * 128 + ty * 8) * N + bx * 128 + tx * 8;
#pragma unroll
    for (int i = 0; i < 8; i++) {
        float cf[8];
#pragma unroll
        for (int j = 0; j < 4; j++) upk2(acc[i][j], cf[2 * j], cf[2 * j + 1]);
        *(float4*)(Cp + (size_t)i * N)     = make_float4(cf[0], cf[1], cf[2], cf[3]);
        *(float4*)(Cp + (size_t)i * N + 4) = make_float4(cf[4], cf[5], cf[6], cf[7]);
    }
}

// ---------------- Flash attention: 128x128 tiles, 512 threads, FFMA2 ----------------
// 16 warps; warp ty owns query rows 8*ty..8*ty+7 exclusively (softmax state in regs).
// Phase A: per-thread 8 rows x 4 kv-cols.  Phase B: per-thread 8 rows x 4 d.
// KP/Vs swizzle: phys_chunk = chunk ^ ((row>>2)&7) (conflict-free for rows 4*tx+j).
// Qt: transposed [d][r], swizzle phys = ((rch ^ ((d>>3)&7))<<2 | rlow).
#define FT 128
#define FLASH_SMEM_BYTES (3 * 128 * 128 * 4)

__global__ __launch_bounds__(512) void flash_kernel(
    const float* __restrict__ q, const float* __restrict__ k,
    const float* __restrict__ v, float* __restrict__ ctx)
{
    extern __shared__ float sm[];
    float* Qt = sm;                  // [128 d][128 r]
    float* KP = sm + 16384;          // K tile, then P
    float* Vs = sm + 32768;          // V tile

    const int qt_ = (int)gridDim.x - 1 - (int)blockIdx.x;  // heavy blocks first
    const int bh = blockIdx.y;
    const int b = bh >> 4;
    const int h = bh & 15;
    const int g = h >> 1;
    const int tid = threadIdx.x;
    const int tx = tid & 31, ty = tid >> 5;
    const int r0 = ty * 8, c0 = tx * 4;

    // ---- load Q tile, pre-scale, store transposed + swizzled ----
    const size_t qbase = (((size_t)b * T_ + (size_t)qt_ * FT) * H_ + h) * D_;
#pragma unroll
    for (int it = 0; it < 8; ++it) {
        int f = it * 512 + tid;
        int r = f >> 5, cd = f & 31;
        float4 val = *(const float4*)(q + qbase + (size_t)r * (H_ * D_) + cd * 4);
        val.x *= SCALE_; val.y *= SCALE_; val.z *= SCALE_; val.w *= SCALE_;
        int d0 = cd * 4;
        int rlow = r & 3, rch = r >> 2;
        Qt[(d0 + 0) * 128 + (((rch ^ (((d0 + 0) >> 3) & 7)) << 2) | rlow)] = val.x;
        Qt[(d0 + 1) * 128 + (((rch ^ (((d0 + 1) >> 3) & 7)) << 2) | rlow)] = val.y;
        Qt[(d0 + 2) * 128 + (((rch ^ (((d0 + 2) >> 3) & 7)) << 2) | rlow)] = val.z;
        Qt[(d0 + 3) * 128 + (((rch ^ (((d0 + 3) >> 3) & 7)) << 2) | rlow)] = val.w;
    }

    float m_[8], l_[8];
#pragma unroll
    for (int i = 0; i < 8; i++) { m_[i] = -1e30f; l_[i] = 0.0f; }

    ull o2[8][2];
#pragma unroll
    for (int i = 0; i < 8; i++) { o2[i][0] = 0ull; o2[i][1] = 0ull; }

    __syncthreads();

    for (int kt = 0; kt <= qt_; ++kt) {
        // ---- load K,V tiles (row-major, swizzled) ----
        const size_t kvbase = (((size_t)b * T_ + (size_t)kt * FT) * KVH_ + g) * D_;
#pragma unroll
        for (int it = 0; it < 8; ++it) {
            int f = it * 512 + tid;
            int r = f >> 5, cd = f & 31;
            size_t off = kvbase + (size_t)r * (KVH_ * D_) + cd * 4;
            int sidx = r * 32 + (cd ^ ((r >> 2) & 7));
            ((float4*)KP)[sidx] = *(const float4*)(k + off);
            ((float4*)Vs)[sidx] = *(const float4*)(v + off);
        }
        __syncthreads();

        // ---- phase A: S = Q K^T (8 rows x 4 cols, rows packed) ----
        ull s2[4][4];
#pragma unroll
        for (int i = 0; i < 4; i++)
#pragma unroll
            for (int j = 0; j < 4; j++) s2[i][j] = 0ull;

#pragma unroll 4
        for (int kc = 0; kc < 32; ++kc) {
            float kf[4][4];
#pragma unroll
            for (int j = 0; j < 4; ++j) {
                int c = c0 + j;
                *(float4*)kf[j] = ((const float4*)KP)[c * 32 + (kc ^ ((c >> 2) & 7))];
            }
#pragma unroll
            for (int kk = 0; kk < 4; ++kk) {
                int kd = kc * 4 + kk;
                int s_ = (kd >> 3) & 7;
                ulonglong2 qa = ((const ulonglong2*)Qt)[kd * 32 + ((ty * 2) ^ s_)];
                ulonglong2 qb = ((const ulonglong2*)Qt)[kd * 32 + ((ty * 2 + 1) ^ s_)];
#pragma unroll
                for (int j = 0; j < 4; ++j) {
                    ull kdp = pk2(kf[j][kk], kf[j][kk]);
                    fma2(s2[0][j], qa.x, kdp);
                    fma2(s2[1][j], qa.y, kdp);
                    fma2(s2[2][j], qb.x, kdp);
                    fma2(s2[3][j], qb.y, kdp);
                }
            }
        }

        // ---- unpack, mask, online softmax (warp-private rows) ----
        float sf[8][4];
#pragma unroll
        for (int p = 0; p < 4; p++)
#pragma unroll
            for (int j = 0; j < 4; j++)
                upk2(s2[p][j], sf[2 * p][j], sf[2 * p + 1][j]);

        const bool diag = (kt == qt_);
        float al_[8];
#pragma unroll
        for (int i = 0; i < 8; ++i) {
            if (diag) {
                int qi = qt_ * FT + r0 + i;
#pragma unroll
                for (int j = 0; j < 4; ++j)
                    if (kt * FT + c0 + j > qi) sf[i][j] = -1e30f;
            }
            float mx = fmaxf(fmaxf(sf[i][0], sf[i][1]), fmaxf(sf[i][2], sf[i][3]));
#pragma unroll
            for (int off = 1; off < 32; off <<= 1)
                mx = fmaxf(mx, __shfl_xor_sync(0xffffffffu, mx, off));
            float mn = fmaxf(m_[i], mx);
            float sum = 0.0f;
#pragma unroll
            for (int j = 0; j < 4; ++j) {
                float p = __expf(sf[i][j] - mn);
                sf[i][j] = p;
                sum += p;
            }
#pragma unroll
            for (int off = 1; off < 32; off <<= 1)
                sum += __shfl_xor_sync(0xffffffffu, sum, off);
            al_[i] = __expf(m_[i] - mn);
            l_[i] = l_[i] * al_[i] + sum;
            m_[i] = mn;
        }
        __syncthreads();   // all warps done reading KP as K

        // ---- store P (own rows only) ----
#pragma unroll
        for (int i = 0; i < 8; ++i) {
            int r = r0 + i;
            ((float4*)KP)[r * 32 + (tx ^ ((r >> 2) & 7))] =
                make_float4(sf[i][0], sf[i][1], sf[i][2], sf[i][3]);
        }
        __syncwarp();      // P rows produced & consumed by this warp only

        // ---- phase B: O = O*alpha + P @ V (8 rows x 4 d, d packed) ----
#pragma unroll
        for (int i = 0; i < 8; ++i) {
            ull ap = pk2(al_[i], al_[i]);
            mul2(o2[i][0], ap);
            mul2(o2[i][1], ap);
        }

#pragma unroll 4
        for (int jc = 0; jc < 32; ++jc) {
            float pv[8][4];
#pragma unroll
            for (int i = 0; i < 8; ++i) {
                int r = r0 + i;
                *(float4*)pv[i] = ((const float4*)KP)[r * 32 + (jc ^ ((r >> 2) & 7))];
            }
            ull vv[4][2];
#pragma unroll
            for (int jj = 0; jj < 4; ++jj) {
                int r = jc * 4 + jj;
                ulonglong2 va = ((const ulonglong2*)Vs)[r * 32 + (tx ^ ((r >> 2) & 7))];
                vv[jj][0] = va.x; vv[jj][1] = va.y;
            }
#pragma unroll
            for (int jj = 0; jj < 4; ++jj)
#pragma unroll
                for (int i = 0; i < 8; ++i) {
                    ull pa = pk2(pv[i][jj], pv[i][jj]);
                    fma2(o2[i][0], pa, vv[jj][0]);
                    fma2(o2[i][1], pa, vv[jj][1]);
                }
        }
        __syncthreads();   // before next tile overwrites KP/Vs
    }

    // ---- epilogue: normalize + store ctx (B,T,H*D); lanes contiguous in d ----
    const size_t obase = (((size_t)b * T_ + (size_t)qt_ * FT + r0) * H_ + h) * D_ + c0;
#pragma unroll
    for (int i = 0; i < 8; ++i) {
        float linv = 1.0f / l_[i];
        float of[4];
        upk2(o2[i][0], of[0], of[1]);
        upk2(o2[i][1], of[2], of[3]);
        *(float4*)(ctx + obase + (size_t)i * (H_ * D_)) =
            make_float4(of[0] * linv, of[1] * linv, of[2] * linv, of[3] * linv);
    }
}

// ---------------- launch ----------------
extern "C" void kernel_launch(void* const* d_in, const int* in_sizes, int n_in,
                              void* d_out, int out_size)
{
    const float* x  = (const float*)d_in[0];
    // d_in[1] = mask (int32 causal tril) — implied by flash kernel, unused
    const float* wq = (const float*)d_in[2];
    const float* wk = (const float*)d_in[3];
    const float* wv = (const float*)d_in[4];
    const float* wo = (const float*)d_in[5];
    float* out = (float*)d_out;

    float *gq, *gk, *gv, *gctx;
    cudaGetSymbolAddress((void**)&gq,   g_q);
    cudaGetSymbolAddress((void**)&gk,   g_k);
    cudaGetSymbolAddress((void**)&gv,   g_v);
    cudaGetSymbolAddress((void**)&gctx, g_ctx);

    const int M = B_ * T_;  // 4096

    rope_table_kernel<<<(T_ * 64) / 256, 256>>>();

    sgemm_kernel<<<dim3((H_ * D_) / 128, M / 128), 256>>>(x, wq, gq, M, H_ * D_, E_);
    sgemm_kernel<<<dim3((KVH_ * D_) / 128, M / 128), 256>>>(x, wk, gk, M, KVH_ * D_, E_);
    sgemm_kernel<<<dim3((KVH_ * D_) / 128, M / 128), 256>>>(x, wv, gv, M, KVH_ * D_, E_);

    int nq4 = B_ * T_ * H_ * (D_ / 4);
    int nk4 = B_ * T_ * KVH_ * (D_ / 4);
    rope_apply_kernel<<<nq4 / 256, 256>>>(gq, H_, nq4);
    rope_apply_kernel<<<nk4 / 256, 256>>>(gk, KVH_, nk4);

    cudaFuncSetAttribute(flash_kernel, cudaFuncAttributeMaxDynamicSharedMemorySize, FLASH_SMEM_BYTES);
    flash_kernel<<<dim3(T_ / FT, B_ * H_), 512, FLASH_SMEM_BYTES>>>(gq, gk, gv, gctx);

    sgemm_kernel<<<dim3(E_ / 128, M / 128), 256>>>(gctx, wo, out, M, E_, H_ * D_);
}

// round 8
// speedup vs baseline: 2.7325x; 1.0013x over previous
#include <cuda_runtime.h>
#include <cuda_bf16.h>
#include <math.h>

// Problem constants
#define B_ 2
#define T_ 2048
#define E_ 2048
#define H_ 16
#define KVH_ 8
#define D_ 128
#define SCALE_ 0.08838834764831845f   // 1/sqrt(128)

typedef unsigned long long ull;

// ---------------- packed f32x2 helpers (Blackwell FFMA2 pipe, rt_SMSP=1) ----------------
__device__ __forceinline__ ull pk2(float lo, float hi) {
    ull r; asm("mov.b64 %0, {%1, %2};" : "=l"(r) : "f"(lo), "f"(hi)); return r;
}
__device__ __forceinline__ void upk2(ull v, float& lo, float& hi) {
    asm("mov.b64 {%0, %1}, %2;" : "=f"(lo), "=f"(hi) : "l"(v));
}
__device__ __forceinline__ void fma2(ull& d, ull a, ull b) {
    asm("fma.rn.f32x2 %0, %1, %2, %0;" : "+l"(d) : "l"(a), "l"(b));
}
__device__ __forceinline__ void mul2(ull& d, ull a) {
    asm("mul.rn.f32x2 %0, %0, %1;" : "+l"(d) : "l"(a));
}

// ---------------- scratch (no allocs allowed) ----------------
__device__ float g_q[(size_t)B_ * T_ * H_ * D_];     // (B,T,H,D)
__device__ float g_k[(size_t)B_ * T_ * KVH_ * D_];   // (B,T,KVH,D)
__device__ float g_v[(size_t)B_ * T_ * KVH_ * D_];
__device__ float g_ctx[(size_t)B_ * T_ * H_ * D_];   // attention output
__device__ float2 g_rope[T_ * 64];                   // (cos,sin) per (t,d2)

// ---------------- RoPE table ----------------
__global__ __launch_bounds__(256) void rope_table_kernel() {
    int idx = blockIdx.x * 256 + threadIdx.x;  // 131072 total
    int t = idx >> 6, d2 = idx & 63;
    double inv = pow(10000.0, -(double)(2 * d2) / 128.0);
    double ang = (double)t * inv;
    g_rope[idx] = make_float2((float)cos(ang), (float)sin(ang));
}

// ---------------- RoPE apply: x (B,T,heads,D), float4 = 2 rotation pairs ----------------
__global__ __launch_bounds__(256) void rope_apply_kernel(float* __restrict__ x, int heads, int total4) {
    int p = blockIdx.x * 256 + threadIdx.x;
    if (p >= total4) return;
    int cd = p & 31;
    int t = (p / (32 * heads)) % T_;
    float4 v = ((const float4*)x)[p];
    float2 r0 = g_rope[t * 64 + cd * 2];
    float2 r1 = g_rope[t * 64 + cd * 2 + 1];
    float a = v.x * r0.x - v.y * r0.y;
    float b = v.x * r0.y + v.y * r0.x;
    float c = v.z * r1.x - v.w * r1.y;
    float d = v.z * r1.y + v.w * r1.x;
    ((float4*)x)[p] = make_float4(a, b, c, d);
}

// ---------------- SGEMM: C[M,N] = A[M,K] @ B[K,N], fp32 via FFMA2 ----------------
// 128x128 tile, BK=16, 256 threads, 8x8 per thread, double-buffered, As padded.
__device__ __forceinline__ void sgemm_compute(
    const float As[16][132], const float Bs[16][128],
    int ty, int tx, ull acc[8][4])
{
#pragma unroll
    for (int kk = 0; kk < 16; kk++) {
        float ar[8];
        *(float4*)(ar)     = *(const float4*)&As[kk][ty * 8];
        *(float4*)(ar + 4) = *(const float4*)&As[kk][ty * 8 + 4];
        ulonglong2 b0 = *(const ulonglong2*)&Bs[kk][tx * 8];
        ulonglong2 b1 = *(const ulonglong2*)&Bs[kk][tx * 8 + 4];
        ull br0 = b0.x, br1 = b0.y, br2 = b1.x, br3 = b1.y;
#pragma unroll
        for (int i = 0; i < 8; i++) {
            ull a2 = pk2(ar[i], ar[i]);
            fma2(acc[i][0], a2, br0);
            fma2(acc[i][1], a2, br1);
            fma2(acc[i][2], a2, br2);
            fma2(acc[i][3], a2, br3);
        }
    }
}

__global__ __launch_bounds__(256, 2) void sgemm_kernel(
    const float* __restrict__ A, const float* __restrict__ Bm,
    float* __restrict__ C, int M, int N, int K)
{
    __shared__ float As[2][16][132];
    __shared__ float Bs[2][16][128];

    const int tid = threadIdx.x;
    const int bx = blockIdx.x, by = blockIdx.y;
    const int arow = tid >> 2;          // 0..63  (second half: +64)
    const int acol = (tid & 3) * 4;     // k-offset within chunk
    const int brow = tid >> 5;          // 0..7   (second half: +8)
    const int bcol = (tid & 31) << 2;
    const int tx = tid & 15, ty = tid >> 4;

    const float* Ag = A + (size_t)(by * 128 + arow) * K + acol;
    const float* Bg = Bm + (size_t)brow * N + bx * 128 + bcol;

    ull acc[8][4];
#pragma unroll
    for (int i = 0; i < 8; i++)
#pragma unroll
        for (int j = 0; j < 4; j++) acc[i][j] = 0ull;

    // preload chunk 0
    float4 av0 = *(const float4*)Ag;
    float4 av1 = *(const float4*)(Ag + (size_t)64 * K);
    Ag += 16;
    float4 bv0 = *(const float4*)Bg;
    float4 bv1 = *(const float4*)(Bg + (size_t)8 * N);
    Bg += (size_t)16 * N;
    As[0][acol + 0][arow] = av0.x;  As[0][acol + 1][arow] = av0.y;
    As[0][acol + 2][arow] = av0.z;  As[0][acol + 3][arow] = av0.w;
    As[0][acol + 0][arow + 64] = av1.x;  As[0][acol + 1][arow + 64] = av1.y;
    As[0][acol + 2][arow + 64] = av1.z;  As[0][acol + 3][arow + 64] = av1.w;
    *(float4*)&Bs[0][brow][bcol] = bv0;
    *(float4*)&Bs[0][brow + 8][bcol] = bv1;
    __syncthreads();

    const int nch = K >> 4;
    for (int c = 1; c < nch; ++c) {
        av0 = *(const float4*)Ag;
        av1 = *(const float4*)(Ag + (size_t)64 * K);
        Ag += 16;
        bv0 = *(const float4*)Bg;
        bv1 = *(const float4*)(Bg + (size_t)8 * N);
        Bg += (size_t)16 * N;
        const int cur = (c - 1) & 1;
        sgemm_compute(As[cur], Bs[cur], ty, tx, acc);
        const int nxt = c & 1;
        As[nxt][acol + 0][arow] = av0.x;  As[nxt][acol + 1][arow] = av0.y;
        As[nxt][acol + 2][arow] = av0.z;  As[nxt][acol + 3][arow] = av0.w;
        As[nxt][acol + 0][arow + 64] = av1.x;  As[nxt][acol + 1][arow + 64] = av1.y;
        As[nxt][acol + 2][arow + 64] = av1.z;  As[nxt][acol + 3][arow + 64] = av1.w;
        *(float4*)&Bs[nxt][brow][bcol] = bv0;
        *(float4*)&Bs[nxt][brow + 8][bcol] = bv1;
        __syncthreads();
    }
    sgemm_compute(As[(nch - 1) & 1], Bs[(nch - 1) & 1], ty, tx, acc);

    float* Cp = C + (size_t)(by * 128 + ty * 8) * N + bx * 128 + tx * 8;
#pragma unroll
    for (int i = 0; i < 8; i++) {
        float cf[8];
#pragma unroll
        for (int j = 0; j < 4; j++) upk2(acc[i][j], cf[2 * j], cf[2 * j + 1]);
        *(float4*)(Cp + (size_t)i * N)     = make_float4(cf[0], cf[1], cf[2], cf[3]);
        *(float4*)(Cp + (size_t)i * N + 4) = make_float4(cf[4], cf[5], cf[6], cf[7]);
    }
}

// ---------------- Flash attention: 128x128 tiles, 512 threads, FFMA2 ----------------
// 16 warps; warp ty owns query rows 8*ty..8*ty+7 exclusively (softmax state in regs).
// Phase A: per-thread 8 rows x 4 kv-cols.  Phase B: per-thread 8 rows x 4 d.
// KP/Vs swizzle: phys_chunk = chunk ^ ((row>>2)&7) (conflict-free for rows 4*tx+j).
// Qt: transposed [d][r], swizzle phys = ((rch ^ ((d>>3)&7))<<2 | rlow).
#define FT 128
#define FLASH_SMEM_BYTES (3 * 128 * 128 * 4)

__global__ __launch_bounds__(512) void flash_kernel(
    const float* __restrict__ q, const float* __restrict__ k,
    const float* __restrict__ v, float* __restrict__ ctx)
{
    extern __shared__ float sm[];
    float* Qt = sm;                  // [128 d][128 r]
    float* KP = sm + 16384;          // K tile, then P
    float* Vs = sm + 32768;          // V tile

    const int qt_ = (int)gridDim.x - 1 - (int)blockIdx.x;  // heavy blocks first
    const int bh = blockIdx.y;
    const int b = bh >> 4;
    const int h = bh & 15;
    const int g = h >> 1;
    const int tid = threadIdx.x;
    const int tx = tid & 31, ty = tid >> 5;
    const int r0 = ty * 8, c0 = tx * 4;

    // ---- load Q tile, pre-scale, store transposed + swizzled ----
    const size_t qbase = (((size_t)b * T_ + (size_t)qt_ * FT) * H_ + h) * D_;
#pragma unroll
    for (int it = 0; it < 8; ++it) {
        int f = it * 512 + tid;
        int r = f >> 5, cd = f & 31;
        float4 val = *(const float4*)(q + qbase + (size_t)r * (H_ * D_) + cd * 4);
        val.x *= SCALE_; val.y *= SCALE_; val.z *= SCALE_; val.w *= SCALE_;
        int d0 = cd * 4;
        int rlow = r & 3, rch = r >> 2;
        Qt[(d0 + 0) * 128 + (((rch ^ (((d0 + 0) >> 3) & 7)) << 2) | rlow)] = val.x;
        Qt[(d0 + 1) * 128 + (((rch ^ (((d0 + 1) >> 3) & 7)) << 2) | rlow)] = val.y;
        Qt[(d0 + 2) * 128 + (((rch ^ (((d0 + 2) >> 3) & 7)) << 2) | rlow)] = val.z;
        Qt[(d0 + 3) * 128 + (((rch ^ (((d0 + 3) >> 3) & 7)) << 2) | rlow)] = val.w;
    }

    float m_[8], l_[8];
#pragma unroll
    for (int i = 0; i < 8; i++) { m_[i] = -1e30f; l_[i] = 0.0f; }

    ull o2[8][2];
#pragma unroll
    for (int i = 0; i < 8; i++) { o2[i][0] = 0ull; o2[i][1] = 0ull; }

    __syncthreads();

    for (int kt = 0; kt <= qt_; ++kt) {
        // ---- load K,V tiles (row-major, swizzled) ----
        const size_t kvbase = (((size_t)b * T_ + (size_t)kt * FT) * KVH_ + g) * D_;
#pragma unroll
        for (int it = 0; it < 8; ++it) {
            int f = it * 512 + tid;
            int r = f >> 5, cd = f & 31;
            size_t off = kvbase + (size_t)r * (KVH_ * D_) + cd * 4;
            int sidx = r * 32 + (cd ^ ((r >> 2) & 7));
            ((float4*)KP)[sidx] = *(const float4*)(k + off);
            ((float4*)Vs)[sidx] = *(const float4*)(v + off);
        }
        __syncthreads();

        // ---- phase A: S = Q K^T (8 rows x 4 cols, rows packed) ----
        ull s2[4][4];
#pragma unroll
        for (int i = 0; i < 4; i++)
#pragma unroll
            for (int j = 0; j < 4; j++) s2[i][j] = 0ull;

#pragma unroll 4
        for (int kc = 0; kc < 32; ++kc) {
            float kf[4][4];
#pragma unroll
            for (int j = 0; j < 4; ++j) {
                int c = c0 + j;
                *(float4*)kf[j] = ((const float4*)KP)[c * 32 + (kc ^ ((c >> 2) & 7))];
            }
#pragma unroll
            for (int kk = 0; kk < 4; ++kk) {
                int kd = kc * 4 + kk;
                int s_ = (kd >> 3) & 7;
                ulonglong2 qa = ((const ulonglong2*)Qt)[kd * 32 + ((ty * 2) ^ s_)];
                ulonglong2 qb = ((const ulonglong2*)Qt)[kd * 32 + ((ty * 2 + 1) ^ s_)];
#pragma unroll
                for (int j = 0; j < 4; ++j) {
                    ull kdp = pk2(kf[j][kk], kf[j][kk]);
                    fma2(s2[0][j], qa.x, kdp);
                    fma2(s2[1][j], qa.y, kdp);
                    fma2(s2[2][j], qb.x, kdp);
                    fma2(s2[3][j], qb.y, kdp);
                }
            }
        }

        // ---- unpack, mask, online softmax (warp-private rows) ----
        float sf[8][4];
#pragma unroll
        for (int p = 0; p < 4; p++)
#pragma unroll
            for (int j = 0; j < 4; j++)
                upk2(s2[p][j], sf[2 * p][j], sf[2 * p + 1][j]);

        const bool diag = (kt == qt_);
        float al_[8];
#pragma unroll
        for (int i = 0; i < 8; ++i) {
            if (diag) {
                int qi = qt_ * FT + r0 + i;
#pragma unroll
                for (int j = 0; j < 4; ++j)
                    if (kt * FT + c0 + j > qi) sf[i][j] = -1e30f;
            }
            float mx = fmaxf(fmaxf(sf[i][0], sf[i][1]), fmaxf(sf[i][2], sf[i][3]));
#pragma unroll
            for (int off = 1; off < 32; off <<= 1)
                mx = fmaxf(mx, __shfl_xor_sync(0xffffffffu, mx, off));
            float mn = fmaxf(m_[i], mx);
            float sum = 0.0f;
#pragma unroll
            for (int j = 0; j < 4; ++j) {
                float p = __expf(sf[i][j] - mn);
                sf[i][j] = p;
                sum += p;
            }
#pragma unroll
            for (int off = 1; off < 32; off <<= 1)
                sum += __shfl_xor_sync(0xffffffffu, sum, off);
            al_[i] = __expf(m_[i] - mn);
            l_[i] = l_[i] * al_[i] + sum;
            m_[i] = mn;
        }
        __syncthreads();   // all warps done reading KP as K

        // ---- store P (own rows only) ----
#pragma unroll
        for (int i = 0; i < 8; ++i) {
            int r = r0 + i;
            ((float4*)KP)[r * 32 + (tx ^ ((r >> 2) & 7))] =
                make_float4(sf[i][0], sf[i][1], sf[i][2], sf[i][3]);
        }
        __syncwarp();      // P rows produced & consumed by this warp only

        // ---- phase B: O = O*alpha + P @ V (8 rows x 4 d, d packed) ----
#pragma unroll
        for (int i = 0; i < 8; ++i) {
            ull ap = pk2(al_[i], al_[i]);
            mul2(o2[i][0], ap);
            mul2(o2[i][1], ap);
        }

#pragma unroll 4
        for (int jc = 0; jc < 32; ++jc) {
            float pv[8][4];
#pragma unroll
            for (int i = 0; i < 8; ++i) {
                int r = r0 + i;
                *(float4*)pv[i] = ((const float4*)KP)[r * 32 + (jc ^ ((r >> 2) & 7))];
            }
            ull vv[4][2];
#pragma unroll
            for (int jj = 0; jj < 4; ++jj) {
                int r = jc * 4 + jj;
                ulonglong2 va = ((const ulonglong2*)Vs)[r * 32 + (tx ^ ((r >> 2) & 7))];
                vv[jj][0] = va.x; vv[jj][1] = va.y;
            }
#pragma unroll
            for (int jj = 0; jj < 4; ++jj)
#pragma unroll
                for (int i = 0; i < 8; ++i) {
                    ull pa = pk2(pv[i][jj], pv[i][jj]);
                    fma2(o2[i][0], pa, vv[jj][0]);
                    fma2(o2[i][1], pa, vv[jj][1]);
                }
        }
        __syncthreads();   // before next tile overwrites KP/Vs
    }

    // ---- epilogue: normalize + store ctx (B,T,H*D); lanes contiguous in d ----
    const size_t obase = (((size_t)b * T_ + (size_t)qt_ * FT + r0) * H_ + h) * D_ + c0;
#pragma unroll
    for (int i = 0; i < 8; ++i) {
        float linv = 1.0f / l_[i];
        float of[4];
        upk2(o2[i][0], of[0], of[1]);
        upk2(o2[i][1], of[2], of[3]);
        *(float4*)(ctx + obase + (size_t)i * (H_ * D_)) =
            make_float4(of[0] * linv, of[1] * linv, of[2] * linv, of[3] * linv);
    }
}

// ---------------- launch ----------------
extern "C" void kernel_launch(void* const* d_in, const int* in_sizes, int n_in,
                              void* d_out, int out_size)
{
    const float* x  = (const float*)d_in[0];
    // d_in[1] = mask (int32 causal tril) — implied by flash kernel, unused
    const float* wq = (const float*)d_in[2];
    const float* wk = (const float*)d_in[3];
    const float* wv = (const float*)d_in[4];
    const float* wo = (const float*)d_in[5];
    float* out = (float*)d_out;

    float *gq, *gk, *gv, *gctx;
    cudaGetSymbolAddress((void**)&gq,   g_q);
    cudaGetSymbolAddress((void**)&gk,   g_k);
    cudaGetSymbolAddress((void**)&gv,   g_v);
    cudaGetSymbolAddress((void**)&gctx, g_ctx);

    const int M = B_ * T_;  // 4096

    rope_table_kernel<<<(T_ * 64) / 256, 256>>>();

    sgemm_kernel<<<dim3((H_ * D_) / 128, M / 128), 256>>>(x, wq, gq, M, H_ * D_, E_);
    sgemm_kernel<<<dim3((KVH_ * D_) / 128, M / 128), 256>>>(x, wk, gk, M, KVH_ * D_, E_);
    sgemm_kernel<<<dim3((KVH_ * D_) / 128, M / 128), 256>>>(x, wv, gv, M, KVH_ * D_, E_);

    int nq4 = B_ * T_ * H_ * (D_ / 4);
    int nk4 = B_ * T_ * KVH_ * (D_ / 4);
    rope_apply_kernel<<<nq4 / 256, 256>>>(gq, H_, nq4);
    rope_apply_kernel<<<nk4 / 256, 256>>>(gk, KVH_, nk4);

    cudaFuncSetAttribute(flash_kernel, cudaFuncAttributeMaxDynamicSharedMemorySize, FLASH_SMEM_BYTES);
    flash_kernel<<<dim3(T_ / FT, B_ * H_), 512, FLASH_SMEM_BYTES>>>(gq, gk, gv, gctx);

    sgemm_kernel<<<dim3(E_ / 128, M / 128), 256>>>(gctx, wo, out, M, E_, H_ * D_);
}